// round 5
// baseline (speedup 1.0000x reference)
#include <cuda_runtime.h>
#include <cstdint>

#define B_TOTAL  131072
#define DIM      1024
#define NH       21
#define ROWS     128
#define KC       16
#define THREADS  128
#define XSTR     20                 // 20*l mod 32 distinct per 8-lane phase
#define NSTAGE   (DIM / KC)         // 64 chunks
#define NBUF     3

__device__ __forceinline__ void cp_async16(uint32_t dst, const void* src) {
    asm volatile("cp.async.cg.shared.global [%0], [%1], 16;\n" :: "r"(dst), "l"(src));
}
__device__ __forceinline__ void cp_commit() {
    asm volatile("cp.async.commit_group;\n" ::: "memory");
}
template<int N> __device__ __forceinline__ void cp_wait() {
    asm volatile("cp.async.wait_group %0;\n" :: "n"(N) : "memory");
}

__global__ __launch_bounds__(THREADS, 6)
void linheads_kernel(const float* __restrict__ x,
                     const float* __restrict__ v_conf,
                     const float* __restrict__ W,
                     const float* __restrict__ bias,
                     float* __restrict__ result,
                     float* __restrict__ out)
{
    __shared__ float xs[NBUF][ROWS * XSTR];   // 3 x 10240 B
    __shared__ float ws[NBUF][NH * KC];       // 3 x 1344 B
    __shared__ float bs[NH];

    const int t = threadIdx.x;
    const long long row0 = (long long)blockIdx.x * ROWS;

    if (t < NH) bs[t] = bias[t];

    unsigned long long acc[NH];
#pragma unroll
    for (int h = 0; h < NH; h++) acc[h] = 0ULL;

    uint32_t xsb[NBUF], wsb[NBUF];
#pragma unroll
    for (int b = 0; b < NBUF; b++) {
        xsb[b] = (uint32_t)__cvta_generic_to_shared(&xs[b][0]);
        wsb[b] = (uint32_t)__cvta_generic_to_shared(&ws[b][0]);
    }

    // stage s -> buffer s % 3.  x: 128 rows x 16 floats = 512 float4 (4/thread).
    auto load_stage = [&](int s) {
        const int k0 = s * KC;
        const uint32_t xb = xsb[s % NBUF];
        const uint32_t wb = wsb[s % NBUF];
#pragma unroll
        for (int i = 0; i < 4; i++) {
            int m   = i * THREADS + t;
            int row = m >> 2;
            int vec = m & 3;
            cp_async16(xb + (uint32_t)(row * XSTR + vec * 4) * 4,
                       &x[(row0 + row) * DIM + k0 + vec * 4]);
        }
        if (t < NH * 4) {                      // 84 float4
            int h = t >> 2, vec = t & 3;
            cp_async16(wb + (uint32_t)(h * KC + vec * 4) * 4,
                       &W[(long long)h * DIM + k0 + vec * 4]);
        }
        cp_commit();
    };

    load_stage(0);
    load_stage(1);

    for (int s = 0; s < NSTAGE; s++) {
        const int buf = s % NBUF;
        cp_wait<1>();                // stage s resident
        __syncthreads();             // also: every warp done computing s-1 -> buf (s+2)%3 free
        if (s + 2 < NSTAGE) load_stage(s + 2);

#pragma unroll
        for (int kk = 0; kk < 4; kk++) {
            ulonglong2 xv = *(const ulonglong2*)&xs[buf][t * XSTR + kk * 4];
#pragma unroll
            for (int h = 0; h < NH; h++) {
                ulonglong2 w = *(const ulonglong2*)&ws[buf][h * KC + kk * 4];
                asm("fma.rn.f32x2 %0, %1, %2, %0;" : "+l"(acc[h]) : "l"(xv.x), "l"(w.x));
                asm("fma.rn.f32x2 %0, %1, %2, %0;" : "+l"(acc[h]) : "l"(xv.y), "l"(w.y));
            }
        }
    }

    // epilogue
    const long long row = row0 + t;
    float res = 0.f;
#pragma unroll
    for (int h = 0; h < NH; h++) {
        float lo = __uint_as_float((unsigned)(acc[h] & 0xffffffffULL));
        float hi = __uint_as_float((unsigned)(acc[h] >> 32));
        float o  = lo + hi + bs[h];
        out[row * NH + h] = o;
        res += o * v_conf[row * NH + h];
    }
    result[row] = res;
}

extern "C" void kernel_launch(void* const* d_in, const int* in_sizes, int n_in,
                              void* d_out, int out_size)
{
    const float* x      = (const float*)d_in[0];   // [B, DIM]
    const float* v_conf = (const float*)d_in[1];   // [B, NH]
    const float* W      = (const float*)d_in[2];   // [NH, DIM]
    const float* bias   = (const float*)d_in[3];   // [NH]

    float* result = (float*)d_out;                 // [B]
    float* out    = (float*)d_out + B_TOTAL;       // [B, NH]

    dim3 grid(B_TOTAL / ROWS);                     // 1024
    linheads_kernel<<<grid, THREADS>>>(x, v_conf, W, bias, result, out);
}

// round 7
// speedup vs baseline: 1.8912x; 1.8912x over previous
#include <cuda_runtime.h>
#include <cuda_bf16.h>
#include <cstdint>

#define B_TOTAL  131072
#define DIM      1024
#define NH       21
#define ROWS     128
#define KC       64                  // fp32 elems per k-chunk
#define NCH      (DIM / KC)          // 16 chunks
#define THREADS  256
#define XSTRB    144                 // bytes per bf16 smem row (128 data + 16 pad)
#define NKS      (DIM / 16)          // 64 k16 steps total
#define NT       3                   // n-tiles of 8 (21 heads padded to 24)

// Pre-packed W fragments (mma.m16n8k16 B-operand layout), hi/lo split
__device__ uint2 g_wf_hi[NKS][NT][32];
__device__ uint2 g_wf_lo[NKS][NT][32];

__global__ void prep_wfrag(const float* __restrict__ W)
{
    int idx = blockIdx.x * blockDim.x + threadIdx.x;
    if (idx >= NKS * NT * 32) return;
    int l  = idx & 31;
    int nt = (idx >> 5) % NT;
    int ks = idx / (NT * 32);
    int n  = nt * 8 + (l >> 2);
    int kb = ks * 16 + 2 * (l & 3);
    float w00 = 0.f, w01 = 0.f, w10 = 0.f, w11 = 0.f;
    if (n < NH) {
        const float* wr = W + (long long)n * DIM + kb;
        w00 = wr[0]; w01 = wr[1]; w10 = wr[8]; w11 = wr[9];
    }
    uint32_t h0, h1, q0, q1;
    asm("cvt.rn.bf16x2.f32 %0, %1, %2;" : "=r"(h0) : "f"(w01), "f"(w00));
    asm("cvt.rn.bf16x2.f32 %0, %1, %2;" : "=r"(h1) : "f"(w11), "f"(w10));
    float r00 = w00 - __uint_as_float(h0 << 16);
    float r01 = w01 - __uint_as_float(h0 & 0xffff0000u);
    float r10 = w10 - __uint_as_float(h1 << 16);
    float r11 = w11 - __uint_as_float(h1 & 0xffff0000u);
    asm("cvt.rn.bf16x2.f32 %0, %1, %2;" : "=r"(q0) : "f"(r01), "f"(r00));
    asm("cvt.rn.bf16x2.f32 %0, %1, %2;" : "=r"(q1) : "f"(r11), "f"(r10));
    g_wf_hi[ks][nt][l] = make_uint2(h0, h1);
    g_wf_lo[ks][nt][l] = make_uint2(q0, q1);
}

__device__ __forceinline__ void cvt_split(float4 v, uint32_t& h01, uint32_t& h23,
                                          uint32_t& l01, uint32_t& l23)
{
    asm("cvt.rn.bf16x2.f32 %0, %1, %2;" : "=r"(h01) : "f"(v.y), "f"(v.x));
    asm("cvt.rn.bf16x2.f32 %0, %1, %2;" : "=r"(h23) : "f"(v.w), "f"(v.z));
    float rx = v.x - __uint_as_float(h01 << 16);
    float ry = v.y - __uint_as_float(h01 & 0xffff0000u);
    float rz = v.z - __uint_as_float(h23 << 16);
    float rw = v.w - __uint_as_float(h23 & 0xffff0000u);
    asm("cvt.rn.bf16x2.f32 %0, %1, %2;" : "=r"(l01) : "f"(ry), "f"(rx));
    asm("cvt.rn.bf16x2.f32 %0, %1, %2;" : "=r"(l23) : "f"(rw), "f"(rz));
}

#define MMA(c, a0, a1, a2, a3, b0, b1)                                          \
    asm("mma.sync.aligned.m16n8k16.row.col.f32.bf16.bf16.f32 "                  \
        "{%0,%1,%2,%3}, {%4,%5,%6,%7}, {%8,%9}, {%0,%1,%2,%3};"                 \
        : "+f"(c[0]), "+f"(c[1]), "+f"(c[2]), "+f"(c[3])                        \
        : "r"(a0), "r"(a1), "r"(a2), "r"(a3), "r"(b0), "r"(b1))

__global__ __launch_bounds__(THREADS, 2)
void linheads_mma_kernel(const float* __restrict__ x,
                         const float* __restrict__ v_conf,
                         const float* __restrict__ bias,
                         float* __restrict__ result,
                         float* __restrict__ out)
{
    __shared__ __align__(16) char xs_hi[ROWS * XSTRB];   // 18432 B
    __shared__ __align__(16) char xs_lo[ROWS * XSTRB];   // 18432 B
    __shared__ float bs[NH];

    const int t   = threadIdx.x;
    const int wid = t >> 5;
    const int l   = t & 31;
    const long long row0 = (long long)blockIdx.x * ROWS;

    if (t < NH) bs[t] = bias[t];

    // C fragments: 1 m16 tile per warp x 3 n8 tiles
    float c[NT][4];
#pragma unroll
    for (int nt = 0; nt < NT; nt++)
#pragma unroll
        for (int i = 0; i < 4; i++) c[nt][i] = 0.f;

    // x staging addresses
    const float* xp = x + (row0 + (t >> 4)) * DIM + (t & 15) * 4;
    const int sbase = (t >> 4) * XSTRB + (t & 15) * 8;

    // A-fragment read base: warp wid owns rows [wid*16, wid*16+16)
    const int abase = (wid * 16 + (l >> 2)) * XSTRB + (l & 3) * 4;

    // ---- preload chunk 0 ----
    float4 cur[8];
#pragma unroll
    for (int i = 0; i < 8; i++) cur[i] = *(const float4*)(xp + i * 16 * DIM);
#pragma unroll
    for (int i = 0; i < 8; i++) {
        uint32_t h01, h23, l01, l23;
        cvt_split(cur[i], h01, h23, l01, l23);
        *(uint2*)(xs_hi + sbase + i * 16 * XSTRB) = make_uint2(h01, h23);
        *(uint2*)(xs_lo + sbase + i * 16 * XSTRB) = make_uint2(l01, l23);
    }
    __syncthreads();

    for (int cch = 0; cch < NCH; cch++) {
        // prefetch next chunk into registers (retires during compute)
        float4 nxt[8];
        if (cch + 1 < NCH) {
#pragma unroll
            for (int i = 0; i < 8; i++)
                nxt[i] = *(const float4*)(xp + (cch + 1) * KC + i * 16 * DIM);
        }

        // ---- compute: 4 k16 steps ----
#pragma unroll
        for (int ks = 0; ks < 4; ks++) {
            const int ab = abase + ks * 32;
            uint32_t ah0 = *(const uint32_t*)(xs_hi + ab);
            uint32_t ah1 = *(const uint32_t*)(xs_hi + ab + 8 * XSTRB);
            uint32_t ah2 = *(const uint32_t*)(xs_hi + ab + 16);
            uint32_t ah3 = *(const uint32_t*)(xs_hi + ab + 8 * XSTRB + 16);
            uint32_t al0 = *(const uint32_t*)(xs_lo + ab);
            uint32_t al1 = *(const uint32_t*)(xs_lo + ab + 8 * XSTRB);
            uint32_t al2 = *(const uint32_t*)(xs_lo + ab + 16);
            uint32_t al3 = *(const uint32_t*)(xs_lo + ab + 8 * XSTRB + 16);
            const int ksg = cch * 4 + ks;
#pragma unroll
            for (int nt = 0; nt < NT; nt++) {
                uint2 bh = g_wf_hi[ksg][nt][l];
                uint2 bl = g_wf_lo[ksg][nt][l];
                MMA(c[nt], ah0, ah1, ah2, ah3, bh.x, bh.y);
                MMA(c[nt], ah0, ah1, ah2, ah3, bl.x, bl.y);
                MMA(c[nt], al0, al1, al2, al3, bh.x, bh.y);
            }
        }
        __syncthreads();

        // ---- stage next chunk ----
        if (cch + 1 < NCH) {
#pragma unroll
            for (int i = 0; i < 8; i++) {
                uint32_t h01, h23, l01, l23;
                cvt_split(nxt[i], h01, h23, l01, l23);
                *(uint2*)(xs_hi + sbase + i * 16 * XSTRB) = make_uint2(h01, h23);
                *(uint2*)(xs_lo + sbase + i * 16 * XSTRB) = make_uint2(l01, l23);
            }
            __syncthreads();
        }
    }

    // ---- epilogue ----
    // thread (wid, l): rows r0 = wid*16 + l/4, r1 = r0+8; cols nt*8 + 2*(l&3) + {0,1}
    const long long rbase = row0 + wid * 16 + (l >> 2);
    float res[2] = {0.f, 0.f};
#pragma unroll
    for (int rr = 0; rr < 2; rr++) {
        const long long row = rbase + rr * 8;
#pragma unroll
        for (int nt = 0; nt < NT; nt++) {
            int col0 = nt * 8 + 2 * (l & 3);
#pragma unroll
            for (int e = 0; e < 2; e++) {
                int col = col0 + e;
                if (col < NH) {
                    float o = c[nt][rr * 2 + e] + bs[col];
                    out[row * NH + col] = o;
                    res[rr] += o * v_conf[row * NH + col];
                }
            }
        }
    }
    // reduce across the 4 lanes sharing a row (l & ~3 .. l|3)
#pragma unroll
    for (int rr = 0; rr < 2; rr++) {
        res[rr] += __shfl_xor_sync(0xffffffffu, res[rr], 1);
        res[rr] += __shfl_xor_sync(0xffffffffu, res[rr], 2);
        if ((l & 3) == 0) result[rbase + rr * 8] = res[rr];
    }
}

extern "C" void kernel_launch(void* const* d_in, const int* in_sizes, int n_in,
                              void* d_out, int out_size)
{
    const float* x      = (const float*)d_in[0];   // [B, DIM]
    const float* v_conf = (const float*)d_in[1];   // [B, NH]
    const float* W      = (const float*)d_in[2];   // [NH, DIM]
    const float* bias   = (const float*)d_in[3];   // [NH]

    float* result = (float*)d_out;                 // [B]
    float* out    = (float*)d_out + B_TOTAL;       // [B, NH]

    prep_wfrag<<<(NKS * NT * 32 + 255) / 256, 256>>>(W);

    dim3 grid(B_TOTAL / ROWS);                     // 1024
    linheads_mma_kernel<<<grid, THREADS>>>(x, v_conf, bias, result, out);
}

// round 8
// speedup vs baseline: 2.3062x; 1.2194x over previous
#include <cuda_runtime.h>
#include <cuda_bf16.h>
#include <cstdint>

#define B_TOTAL  131072
#define DIM      1024
#define NH       21
#define THREADS  128
#define WROWS    16                  // rows per warp
#define BROWS    64                  // rows per block (4 warps)
#define NCH      16                  // K chunks of 64
#define NKS      (DIM / 16)          // 64 k16 steps
#define NT       3                   // n-tiles of 8 (21 -> 24)

// Pre-packed W fragments (mma.m16n8k16 B layout), hi/lo split
__device__ uint2 g_wf_hi[NKS][NT][32];
__device__ uint2 g_wf_lo[NKS][NT][32];

__global__ void prep_wfrag(const float* __restrict__ W)
{
    int idx = blockIdx.x * blockDim.x + threadIdx.x;
    if (idx >= NKS * NT * 32) return;
    int l  = idx & 31;
    int nt = (idx >> 5) % NT;
    int ks = idx / (NT * 32);
    int n  = nt * 8 + (l >> 2);
    int kb = ks * 16 + 2 * (l & 3);
    float w00 = 0.f, w01 = 0.f, w10 = 0.f, w11 = 0.f;
    if (n < NH) {
        const float* wr = W + (long long)n * DIM + kb;
        w00 = wr[0]; w01 = wr[1]; w10 = wr[8]; w11 = wr[9];
    }
    uint32_t h0, h1, q0, q1;
    asm("cvt.rn.bf16x2.f32 %0, %1, %2;" : "=r"(h0) : "f"(w01), "f"(w00));
    asm("cvt.rn.bf16x2.f32 %0, %1, %2;" : "=r"(h1) : "f"(w11), "f"(w10));
    float r00 = w00 - __uint_as_float(h0 << 16);
    float r01 = w01 - __uint_as_float(h0 & 0xffff0000u);
    float r10 = w10 - __uint_as_float(h1 << 16);
    float r11 = w11 - __uint_as_float(h1 & 0xffff0000u);
    asm("cvt.rn.bf16x2.f32 %0, %1, %2;" : "=r"(q0) : "f"(r01), "f"(r00));
    asm("cvt.rn.bf16x2.f32 %0, %1, %2;" : "=r"(q1) : "f"(r11), "f"(r10));
    g_wf_hi[ks][nt][l] = make_uint2(h0, h1);
    g_wf_lo[ks][nt][l] = make_uint2(q0, q1);
}

// float2 -> packed bf16x2 hi + residual lo
__device__ __forceinline__ void cvt2(float2 v, uint32_t& h, uint32_t& q)
{
    asm("cvt.rn.bf16x2.f32 %0, %1, %2;" : "=r"(h) : "f"(v.y), "f"(v.x));
    float rx = v.x - __uint_as_float(h << 16);
    float ry = v.y - __uint_as_float(h & 0xffff0000u);
    asm("cvt.rn.bf16x2.f32 %0, %1, %2;" : "=r"(q) : "f"(ry), "f"(rx));
}

#define MMA(c, a0, a1, a2, a3, b0, b1)                                          \
    asm("mma.sync.aligned.m16n8k16.row.col.f32.bf16.bf16.f32 "                  \
        "{%0,%1,%2,%3}, {%4,%5,%6,%7}, {%8,%9}, {%0,%1,%2,%3};"                 \
        : "+f"(c[0]), "+f"(c[1]), "+f"(c[2]), "+f"(c[3])                        \
        : "r"(a0), "r"(a1), "r"(a2), "r"(a3), "r"(b0), "r"(b1))

__global__ __launch_bounds__(THREADS, 4)
void linheads_mma_kernel(const float* __restrict__ x,
                         const float* __restrict__ v_conf,
                         const float* __restrict__ bias,
                         float* __restrict__ result,
                         float* __restrict__ out)
{
    const int t   = threadIdx.x;
    const int wid = t >> 5;
    const int l   = t & 31;

    // this warp's 16-row tile; lane reads rows rA = base + l/4 and rB = rA + 8
    const long long rA = (long long)blockIdx.x * BROWS + wid * WROWS + (l >> 2);
    const float* pA = x + rA * DIM + 2 * (l & 3);
    const float* pB = pA + 8 * DIM;

    float c[NT][4];
#pragma unroll
    for (int nt = 0; nt < NT; nt++)
#pragma unroll
        for (int i = 0; i < 4; i++) c[nt][i] = 0.f;

    // pair slots per chunk: p = 4*ks + {0:(rA,k) 1:(rB,k) 2:(rA,k+8) 3:(rB,k+8)}
    float2 cur[16];
#pragma unroll
    for (int ks = 0; ks < 4; ks++) {
        cur[4 * ks + 0] = *(const float2*)(pA + 16 * ks);
        cur[4 * ks + 1] = *(const float2*)(pB + 16 * ks);
        cur[4 * ks + 2] = *(const float2*)(pA + 16 * ks + 8);
        cur[4 * ks + 3] = *(const float2*)(pB + 16 * ks + 8);
    }

    for (int cch = 0; cch < NCH; cch++) {
        // prefetch next chunk (retires during this chunk's compute)
        float2 nxt[16];
        if (cch + 1 < NCH) {
            const int k0 = (cch + 1) * 64;
#pragma unroll
            for (int ks = 0; ks < 4; ks++) {
                nxt[4 * ks + 0] = *(const float2*)(pA + k0 + 16 * ks);
                nxt[4 * ks + 1] = *(const float2*)(pB + k0 + 16 * ks);
                nxt[4 * ks + 2] = *(const float2*)(pA + k0 + 16 * ks + 8);
                nxt[4 * ks + 3] = *(const float2*)(pB + k0 + 16 * ks + 8);
            }
        }

        // convert current chunk to bf16 hi/lo
        uint32_t ah[16], al[16];
#pragma unroll
        for (int p = 0; p < 16; p++) cvt2(cur[p], ah[p], al[p]);

        // 4 k16 steps x (3 n-tiles x 3 split MMAs)
#pragma unroll
        for (int ks = 0; ks < 4; ks++) {
            const int ksg = cch * 4 + ks;
            const int p = 4 * ks;
#pragma unroll
            for (int nt = 0; nt < NT; nt++) {
                uint2 bh = g_wf_hi[ksg][nt][l];
                uint2 bl = g_wf_lo[ksg][nt][l];
                MMA(c[nt], ah[p], ah[p + 1], ah[p + 2], ah[p + 3], bh.x, bh.y);
                MMA(c[nt], ah[p], ah[p + 1], ah[p + 2], ah[p + 3], bl.x, bl.y);
                MMA(c[nt], al[p], al[p + 1], al[p + 2], al[p + 3], bh.x, bh.y);
            }
        }

#pragma unroll
        for (int p = 0; p < 16; p++) cur[p] = nxt[p];
    }

    // ---- epilogue: lane owns rows rA, rA+8; cols nt*8 + 2*(l&3) + {0,1} ----
    float res[2] = {0.f, 0.f};
#pragma unroll
    for (int rr = 0; rr < 2; rr++) {
        const long long row = rA + rr * 8;
#pragma unroll
        for (int nt = 0; nt < NT; nt++) {
            int col0 = nt * 8 + 2 * (l & 3);
#pragma unroll
            for (int e = 0; e < 2; e++) {
                int col = col0 + e;
                if (col < NH) {
                    float o = c[nt][rr * 2 + e] + bias[col];
                    out[row * NH + col] = o;
                    res[rr] += o * v_conf[row * NH + col];
                }
            }
        }
    }
#pragma unroll
    for (int rr = 0; rr < 2; rr++) {
        res[rr] += __shfl_xor_sync(0xffffffffu, res[rr], 1);
        res[rr] += __shfl_xor_sync(0xffffffffu, res[rr], 2);
        if ((l & 3) == 0) result[rA + rr * 8] = res[rr];
    }
}

extern "C" void kernel_launch(void* const* d_in, const int* in_sizes, int n_in,
                              void* d_out, int out_size)
{
    const float* x      = (const float*)d_in[0];   // [B, DIM]
    const float* v_conf = (const float*)d_in[1];   // [B, NH]
    const float* W      = (const float*)d_in[2];   // [NH, DIM]
    const float* bias   = (const float*)d_in[3];   // [NH]

    float* result = (float*)d_out;                 // [B]
    float* out    = (float*)d_out + B_TOTAL;       // [B, NH]

    prep_wfrag<<<(NKS * NT * 32 + 255) / 256, 256>>>(W);

    dim3 grid(B_TOTAL / BROWS);                    // 2048
    linheads_mma_kernel<<<grid, THREADS>>>(x, v_conf, bias, result, out);
}

// round 9
// speedup vs baseline: 2.5707x; 1.1147x over previous
#include <cuda_runtime.h>
#include <cuda_bf16.h>
#include <cstdint>

#define B_TOTAL  131072
#define DIM      1024
#define NH       21
#define THREADS  128
#define WROWS    32                  // rows per warp (2 m16 tiles)
#define BROWS    128                 // rows per block (4 warps)
#define NKS      (DIM / 16)          // 64 k16 steps
#define NT       3                   // n-tiles of 8 (21 -> 24)

// W fragments, k-permuted to match float4 lane loads.
// uint4 = {b0_hi, b1_hi, b0_lo, b1_lo}
__device__ uint4 g_wf[NKS][NT][32];

__global__ void prep_wfrag(const float* __restrict__ W)
{
    int idx = blockIdx.x * blockDim.x + threadIdx.x;
    if (idx >= NKS * NT * 32) return;
    int l  = idx & 31;
    int nt = (idx >> 5) % NT;
    int ks = idx / (NT * 32);
    int n  = nt * 8 + (l >> 2);
    int col = ks * 16 + 4 * (l & 3);
    float4 wv = make_float4(0.f, 0.f, 0.f, 0.f);
    if (n < NH) wv = *(const float4*)&W[(long long)n * DIM + col];
    uint32_t h0, h1, q0, q1;
    asm("cvt.rn.bf16x2.f32 %0, %1, %2;" : "=r"(h0) : "f"(wv.y), "f"(wv.x));
    asm("cvt.rn.bf16x2.f32 %0, %1, %2;" : "=r"(h1) : "f"(wv.w), "f"(wv.z));
    float rx = wv.x - __uint_as_float(h0 << 16);
    float ry = wv.y - __uint_as_float(h0 & 0xffff0000u);
    float rz = wv.z - __uint_as_float(h1 << 16);
    float rw = wv.w - __uint_as_float(h1 & 0xffff0000u);
    asm("cvt.rn.bf16x2.f32 %0, %1, %2;" : "=r"(q0) : "f"(ry), "f"(rx));
    asm("cvt.rn.bf16x2.f32 %0, %1, %2;" : "=r"(q1) : "f"(rw), "f"(rz));
    g_wf[ks][nt][l] = make_uint4(h0, h1, q0, q1);
}

#define MMA(c, a0, a1, a2, a3, b0, b1)                                          \
    asm("mma.sync.aligned.m16n8k16.row.col.f32.bf16.bf16.f32 "                  \
        "{%0,%1,%2,%3}, {%4,%5,%6,%7}, {%8,%9}, {%0,%1,%2,%3};"                 \
        : "+f"(c[0]), "+f"(c[1]), "+f"(c[2]), "+f"(c[3])                        \
        : "r"(a0), "r"(a1), "r"(a2), "r"(a3), "r"(b0), "r"(b1))

// float4 (4 consecutive k) -> two packed bf16x2 hi + two residual lo
__device__ __forceinline__ void cvt4(float4 v, uint32_t& h0, uint32_t& h1,
                                     uint32_t& q0, uint32_t& q1)
{
    asm("cvt.rn.bf16x2.f32 %0, %1, %2;" : "=r"(h0) : "f"(v.y), "f"(v.x));
    asm("cvt.rn.bf16x2.f32 %0, %1, %2;" : "=r"(h1) : "f"(v.w), "f"(v.z));
    float rx = v.x - __uint_as_float(h0 << 16);
    float ry = v.y - __uint_as_float(h0 & 0xffff0000u);
    float rz = v.z - __uint_as_float(h1 << 16);
    float rw = v.w - __uint_as_float(h1 & 0xffff0000u);
    asm("cvt.rn.bf16x2.f32 %0, %1, %2;" : "=r"(q0) : "f"(ry), "f"(rx));
    asm("cvt.rn.bf16x2.f32 %0, %1, %2;" : "=r"(q1) : "f"(rw), "f"(rz));
}

__global__ __launch_bounds__(THREADS, 4)
void linheads_mma_kernel(const float* __restrict__ x,
                         const float* __restrict__ v_conf,
                         const float* __restrict__ bias,
                         float* __restrict__ result,
                         float* __restrict__ out)
{
    const int t   = threadIdx.x;
    const int wid = t >> 5;
    const int l   = t & 31;

    const long long wb = (long long)blockIdx.x * BROWS + wid * WROWS;
    // frag rows (r, r+8) <-> global rows (2r, 2r+1); lane quad-row r = l>>2
    const float* p00 = x + (wb + 2 * (l >> 2)) * DIM + 4 * (l & 3);

    float c[2][NT][4];
#pragma unroll
    for (int mt = 0; mt < 2; mt++)
#pragma unroll
        for (int nt = 0; nt < NT; nt++)
#pragma unroll
            for (int i = 0; i < 4; i++) c[mt][nt][i] = 0.f;

    // cur[mt*2 + rr]: float4 at (row wb + 16mt + 2(l>>2) + rr, k 16ks + 4(l&3))
    float4 cur[4];
    cur[0] = __ldcs((const float4*)(p00));
    cur[1] = __ldcs((const float4*)(p00 + DIM));
    cur[2] = __ldcs((const float4*)(p00 + 16 * DIM));
    cur[3] = __ldcs((const float4*)(p00 + 17 * DIM));

#pragma unroll 2
    for (int ks = 0; ks < NKS; ks++) {
        float4 nxt[4];
        if (ks + 1 < NKS) {
            const int o = (ks + 1) * 16;
            nxt[0] = __ldcs((const float4*)(p00 + o));
            nxt[1] = __ldcs((const float4*)(p00 + DIM + o));
            nxt[2] = __ldcs((const float4*)(p00 + 16 * DIM + o));
            nxt[3] = __ldcs((const float4*)(p00 + 17 * DIM + o));
        }

        // convert: a0 = hi(row rr0, k 4q..4q+1), a1 = row rr1, a2/a3 = k+2..3
        uint32_t ah[2][4], al[2][4];
#pragma unroll
        for (int mt = 0; mt < 2; mt++) {
            cvt4(cur[mt * 2 + 0], ah[mt][0], ah[mt][2], al[mt][0], al[mt][2]);
            cvt4(cur[mt * 2 + 1], ah[mt][1], ah[mt][3], al[mt][1], al[mt][3]);
        }

#pragma unroll
        for (int nt = 0; nt < NT; nt++) {
            uint4 wf = g_wf[ks][nt][l];
#pragma unroll
            for (int mt = 0; mt < 2; mt++) {
                MMA(c[mt][nt], ah[mt][0], ah[mt][1], ah[mt][2], ah[mt][3], wf.x, wf.y);
                MMA(c[mt][nt], ah[mt][0], ah[mt][1], ah[mt][2], ah[mt][3], wf.z, wf.w);
                MMA(c[mt][nt], al[mt][0], al[mt][1], al[mt][2], al[mt][3], wf.x, wf.y);
            }
        }

#pragma unroll
        for (int p = 0; p < 4; p++) cur[p] = nxt[p];
    }

    // ---- epilogue ----
    // c[mt][nt][rr*2+e]: row = wb + 16mt + 2(l>>2) + rr, col = nt*8 + 2(l&3) + e
#pragma unroll
    for (int mt = 0; mt < 2; mt++) {
#pragma unroll
        for (int rr = 0; rr < 2; rr++) {
            const long long row = wb + 16 * mt + 2 * (l >> 2) + rr;
            float res = 0.f;
#pragma unroll
            for (int nt = 0; nt < NT; nt++) {
                int col0 = nt * 8 + 2 * (l & 3);
#pragma unroll
                for (int e = 0; e < 2; e++) {
                    int col = col0 + e;
                    if (col < NH) {
                        float o = c[mt][nt][rr * 2 + e] + bias[col];
                        out[row * NH + col] = o;
                        res += o * v_conf[row * NH + col];
                    }
                }
            }
            res += __shfl_xor_sync(0xffffffffu, res, 1);
            res += __shfl_xor_sync(0xffffffffu, res, 2);
            if ((l & 3) == 0) result[row] = res;
        }
    }
}

extern "C" void kernel_launch(void* const* d_in, const int* in_sizes, int n_in,
                              void* d_out, int out_size)
{
    const float* x      = (const float*)d_in[0];   // [B, DIM]
    const float* v_conf = (const float*)d_in[1];   // [B, NH]
    const float* W      = (const float*)d_in[2];   // [NH, DIM]
    const float* bias   = (const float*)d_in[3];   // [NH]

    float* result = (float*)d_out;                 // [B]
    float* out    = (float*)d_out + B_TOTAL;       // [B, NH]

    prep_wfrag<<<(NKS * NT * 32 + 255) / 256, 256>>>(W);

    dim3 grid(B_TOTAL / BROWS);                    // 1024
    linheads_mma_kernel<<<grid, THREADS>>>(x, v_conf, bias, result, out);
}